// round 16
// baseline (speedup 1.0000x reference)
#include <cuda_runtime.h>
#include <cuda_bf16.h>
#include <cstdint>
#include <math.h>

// ---------------- problem constants ----------------
#define T_LEN   4096
#define R_LEN   49
#define D_LEN   512
#define N_SEG   256
#define N_CLASS 106
#define N_CAT   18

#define FEAT_FLOATS (R_LEN * D_LEN)       // 25088

// output layout: keysteps[106*256], cats[18], alphas_sp[4096*49], alphas_ks[106]
#define OUT_KS   0
#define OUT_CATS (N_CLASS * N_SEG)
#define OUT_ASP  (OUT_CATS + N_CAT)
#define OUT_AKS  (OUT_ASP + T_LEN * R_LEN)

#define NB 128     // tail grid size (co-resident: 128 <= 148 SMs at 1 block/SM)

// ---------------- scratch ----------------
__device__ float g_segsum[N_SEG * D_LEN];     // [s][d]
__device__ float g_cnt[N_SEG];
__device__ float g_w1t[3 * D_LEN * D_LEN];    // w1 transposed: [k][i][o]
__device__ float g_hacc[D_LEN * N_SEG];       // conv1 pre-activation accumulator: [o][s]
__device__ float g_att[N_CLASS * N_SEG];      // softmax over classes: [m][s]
__device__ float g_fk[N_CLASS * D_LEN];       // f_keysteps: [m][d]
__device__ unsigned g_bar[4];                 // grid barrier counters

// ---------------- K_prep: zero accumulators + transpose w1 + reset barriers ----------------
__global__ void k_prep(const float* __restrict__ w1) {
    __shared__ float tl[32][33];
    const int z = blockIdx.z;
    const int tx = threadIdx.x, ty = threadIdx.y;
    if (z < 3) {
        const int o0 = blockIdx.x * 32, i0 = blockIdx.y * 32, k = z;
        #pragma unroll
        for (int j = ty; j < 32; j += 8)
            tl[j][tx] = w1[(size_t)(o0 + j) * (D_LEN * 3) + (i0 + tx) * 3 + k];
        __syncthreads();
        #pragma unroll
        for (int j = ty; j < 32; j += 8)
            g_w1t[((size_t)k * D_LEN + i0 + j) * D_LEN + o0 + tx] = tl[tx][j];
    } else {
        const int bid = blockIdx.y * 16 + blockIdx.x;   // 0..255
        const int i = bid * 256 + ty * 32 + tx;         // 0..65535
        g_segsum[i] = 0.f;           g_hacc[i] = 0.f;
        g_segsum[i + 65536] = 0.f;   g_hacc[i + 65536] = 0.f;
        if (i < N_SEG) g_cnt[i] = 0.f;
        if (i < 4) g_bar[i] = 0u;
    }
}

// ---------------- K1: spatial attention + segment accumulation (champion; unchanged) ----------------
__global__ void __launch_bounds__(256)
k_spatial(const float* __restrict__ feature,
          const int* __restrict__ seg_ids,
          const float* __restrict__ att_w,
          const float* __restrict__ att_b,
          float* __restrict__ alphas_out) {
    __shared__ float sv[64];

    const int t = blockIdx.x;
    const int tid = threadIdx.x;
    const int warp = tid >> 5, lane = tid & 31;
    const float* fbase = feature + (size_t)t * FEAT_FLOATS;
    const float4* f4 = (const float4*)fbase;

    float4 w4[4];
    {
        const float4* wv = (const float4*)att_w;
        #pragma unroll
        for (int j = 0; j < 4; j++) w4[j] = wv[lane + 32 * j];
    }
    const float ab = att_b[0];

    for (int r = warp; r < R_LEN; r += 8) {
        const float4* fr = f4 + r * 128;
        float acc = 0.f;
        #pragma unroll
        for (int j = 0; j < 4; j++) {
            float4 v = fr[lane + 32 * j];
            acc += v.x * w4[j].x + v.y * w4[j].y + v.z * w4[j].z + v.w * w4[j].w;
        }
        #pragma unroll
        for (int o = 16; o; o >>= 1) acc += __shfl_xor_sync(0xffffffffu, acc, o);
        if (!lane) sv[r] = acc + ab;
    }
    __syncthreads();

    if (warp == 0) {
        float v0 = sv[lane];
        float v1 = (lane + 32 < R_LEN) ? sv[lane + 32] : -1e30f;
        float mx = fmaxf(v0, v1);
        #pragma unroll
        for (int o = 16; o; o >>= 1) mx = fmaxf(mx, __shfl_xor_sync(0xffffffffu, mx, o));
        float e0 = __expf(v0 - mx);
        float e1 = (lane + 32 < R_LEN) ? __expf(v1 - mx) : 0.f;
        float sum = e0 + e1;
        #pragma unroll
        for (int o = 16; o; o >>= 1) sum += __shfl_xor_sync(0xffffffffu, sum, o);
        float inv = 1.f / sum;
        {
            float a = e0 * inv;
            sv[lane] = a;
            alphas_out[t * R_LEN + lane] = a;
        }
        if (lane + 32 < R_LEN) {
            float a = e1 * inv;
            sv[lane + 32] = a;
            alphas_out[t * R_LEN + lane + 32] = a;
        }
    }
    __syncthreads();

    {
        const float2* f2 = (const float2*)fbase;
        float ax = 0.f, ay = 0.f;
        #pragma unroll 7
        for (int r = 0; r < R_LEN; r++) {
            float a = sv[r];
            float2 v = f2[r * 256 + tid];
            ax += v.x * a;
            ay += v.y * a;
        }
        const int seg = __ldg(&seg_ids[t]);
        float* dst = &g_segsum[seg * D_LEN + tid * 2];
        atomicAdd(dst + 0, ax);
        atomicAdd(dst + 1, ay);
        if (tid == 0) atomicAdd(&g_cnt[seg], 1.f);
    }
}

// ---------------- grid barrier (all NB blocks co-resident) ----------------
__device__ __forceinline__ void grid_barrier(int idx) {
    __syncthreads();
    if (threadIdx.x == 0) {
        __threadfence();
        atomicAdd(&g_bar[idx], 1u);
        while (*(volatile unsigned*)&g_bar[idx] < (unsigned)NB) { __nanosleep(32); }
        __threadfence();
    }
    __syncthreads();
}

// ---------------- K_tail: conv1 -> conv2+softmax -> fk -> final, one kernel ----------------
// 128 blocks x 512 threads; phase 1 software-pipelined (register prefetch).
#define CWW 68    // Wt row stride (32x64 tile)
#define CWX 132   // Xt row stride (32x128 tile)
#define P2J 4     // conv2 columns per block
#define P2S 5     // conv2 smem pad stride
__global__ void __launch_bounds__(512, 1)
k_tail(const float* __restrict__ b1,
       const float* __restrict__ w2,
       const float* __restrict__ b2,
       const float* __restrict__ att2_w,
       const float* __restrict__ att2_b,
       const float* __restrict__ cls_w,
       const float* __restrict__ cls_b,
       float* __restrict__ out_ks,
       float* __restrict__ out_aks,
       float* __restrict__ out_cats) {
    __shared__ float SMEM[6600];   // 26.4KB, aliased per phase

    const int bid = blockIdx.x;
    const int tid = threadIdx.x;
    const int warp = tid >> 5, lane = tid & 31;

    // ===================== phase 1: conv1 (split-K GEMM, 128 jobs, pipelined) =====================
    // job = (8 o-tiles of 64) x (2 s-tiles of 128) x (8 splits of 6 k-chunks)
    {
        float* Wt   = SMEM;                  // 32 x 64 (stride 68)
        float* Xt   = SMEM + 32 * CWW;       // 32 x 128 (stride 132)
        float* icnt = Xt + 32 * CWX;         // 130 entries

        const int ot = bid & 7;
        const int st = (bid >> 3) & 1;
        const int sp = bid >> 4;             // 0..7
        const int o0 = ot * 64, s0 = st * 128;
        const int tx = tid & 31, ty = tid >> 5;
        const int c0 = sp * 6;

        float acc[4][4];
        #pragma unroll
        for (int a = 0; a < 4; a++)
            #pragma unroll
            for (int b = 0; b < 4; b++) acc[a][b] = 0.f;

        if (tid < 130) {
            int sc = s0 + tid - 1;
            float c = (sc >= 0 && sc < N_SEG) ? fmaxf(g_cnt[sc], 1.f) : 1.f;
            icnt[tid] = 1.f / c;
        }
        __syncthreads();

        // prologue: load chunk c0 into smem directly
        {
            const int k = c0 >> 4;
            const int ic = (c0 & 15) * 32;
            #pragma unroll
            for (int q = 0; q < 4; q++) {
                int l = tid + q * 512;
                int ii = l >> 6, oo = l & 63;
                Wt[ii * CWW + oo] = g_w1t[((size_t)k * D_LEN + ic + ii) * D_LEN + o0 + oo];
            }
            #pragma unroll
            for (int q = 0; q < 8; q++) {
                int l = tid + q * 512;
                int ii = l & 31, ss = l >> 5;
                int sc = s0 + ss + k - 1;
                float v = (sc >= 0 && sc < N_SEG) ? g_segsum[sc * D_LEN + ic + ii] : 0.f;
                Xt[ii * CWX + ss] = v * icnt[ss + k];
            }
        }
        __syncthreads();

        #pragma unroll 1
        for (int i = 0; i < 6; i++) {
            // prefetch chunk c0+i+1 into registers (latency hidden under compute)
            float wreg[4], xreg[8];
            int knext = 0;
            if (i < 5) {
                const int cn = c0 + i + 1;
                knext = cn >> 4;
                const int icn = (cn & 15) * 32;
                #pragma unroll
                for (int q = 0; q < 4; q++) {
                    int l = tid + q * 512;
                    int ii = l >> 6, oo = l & 63;
                    wreg[q] = g_w1t[((size_t)knext * D_LEN + icn + ii) * D_LEN + o0 + oo];
                }
                #pragma unroll
                for (int q = 0; q < 8; q++) {
                    int l = tid + q * 512;
                    int ii = l & 31, ss = l >> 5;
                    int sc = s0 + ss + knext - 1;
                    xreg[q] = (sc >= 0 && sc < N_SEG) ? g_segsum[sc * D_LEN + icn + ii] : 0.f;
                }
            }

            // compute current chunk from smem
            #pragma unroll
            for (int ii = 0; ii < 32; ii++) {
                float4 wv = *(const float4*)&Wt[ii * CWW + ty * 4];
                float4 xv = *(const float4*)&Xt[ii * CWX + tx * 4];
                acc[0][0] += wv.x * xv.x; acc[0][1] += wv.x * xv.y;
                acc[0][2] += wv.x * xv.z; acc[0][3] += wv.x * xv.w;
                acc[1][0] += wv.y * xv.x; acc[1][1] += wv.y * xv.y;
                acc[1][2] += wv.y * xv.z; acc[1][3] += wv.y * xv.w;
                acc[2][0] += wv.z * xv.x; acc[2][1] += wv.z * xv.y;
                acc[2][2] += wv.z * xv.z; acc[2][3] += wv.z * xv.w;
                acc[3][0] += wv.w * xv.x; acc[3][1] += wv.w * xv.y;
                acc[3][2] += wv.w * xv.z; acc[3][3] += wv.w * xv.w;
            }
            __syncthreads();   // all reads of smem done

            if (i < 5) {
                #pragma unroll
                for (int q = 0; q < 4; q++) {
                    int l = tid + q * 512;
                    int ii = l >> 6, oo = l & 63;
                    Wt[ii * CWW + oo] = wreg[q];
                }
                #pragma unroll
                for (int q = 0; q < 8; q++) {
                    int l = tid + q * 512;
                    int ii = l & 31, ss = l >> 5;
                    Xt[ii * CWX + ss] = xreg[q] * icnt[ss + knext];
                }
                __syncthreads();   // stores visible before next compute
            }
        }
        #pragma unroll
        for (int a = 0; a < 4; a++) {
            float* dst = &g_hacc[(o0 + ty * 4 + a) * N_SEG + s0 + tx * 4];
            #pragma unroll
            for (int b = 0; b < 4; b++) atomicAdd(dst + b, acc[a][b]);
        }
    }
    grid_barrier(0);

    // ===================== phase 2: bias+relu + conv2 + class softmax (64 jobs) =====================
    if (bid < 64) {
        float* hc = SMEM;                     // [512][P2S]
        float* lg = SMEM + D_LEN * P2S;       // [112][P2S]
        const int s0 = bid * P2J;

        for (int l = tid; l < D_LEN * P2J; l += 512) {
            int i = l >> 2, j = l & 3;
            hc[i * P2S + j] = fmaxf(g_hacc[i * N_SEG + s0 + j] + b1[i], 0.f);
        }
        __syncthreads();

        for (int m = warp; m < N_CLASS; m += 16) {
            float acc[P2J] = {0.f, 0.f, 0.f, 0.f};
            const float* wm = w2 + m * D_LEN;
            #pragma unroll 4
            for (int i = lane; i < D_LEN; i += 32) {
                float wv = wm[i];
                const float* hp = &hc[i * P2S];
                #pragma unroll
                for (int j = 0; j < P2J; j++) acc[j] += wv * hp[j];
            }
            #pragma unroll
            for (int j = 0; j < P2J; j++) {
                float a = acc[j];
                #pragma unroll
                for (int o = 16; o; o >>= 1) a += __shfl_xor_sync(0xffffffffu, a, o);
                acc[j] = a;
            }
            if (!lane) {
                float bb = b2[m];
                #pragma unroll
                for (int j = 0; j < P2J; j++) lg[m * P2S + j] = acc[j] + bb;
            }
        }
        __syncthreads();

        if (warp < P2J) {
            int j = warp;
            int s = s0 + j;
            float v[4], mx = -1e30f;
            #pragma unroll
            for (int q = 0; q < 4; q++) {
                int m = lane + 32 * q;
                v[q] = (m < N_CLASS) ? lg[m * P2S + j] : -1e30f;
                mx = fmaxf(mx, v[q]);
            }
            #pragma unroll
            for (int o = 16; o; o >>= 1) mx = fmaxf(mx, __shfl_xor_sync(0xffffffffu, mx, o));
            float e[4], sum = 0.f;
            #pragma unroll
            for (int q = 0; q < 4; q++) {
                int m = lane + 32 * q;
                e[q] = (m < N_CLASS) ? __expf(v[q] - mx) : 0.f;
                sum += e[q];
            }
            #pragma unroll
            for (int o = 16; o; o >>= 1) sum += __shfl_xor_sync(0xffffffffu, sum, o);
            float inv = 1.f / sum;
            #pragma unroll
            for (int q = 0; q < 4; q++) {
                int m = lane + 32 * q;
                if (m < N_CLASS) {
                    out_ks[m * N_SEG + s] = v[q];
                    g_att[m * N_SEG + s] = e[q] * inv;
                }
            }
        }
    }
    grid_barrier(1);

    // ===================== phase 3: f_keysteps (27 jobs) =====================
    if (bid < 27) {
        float (*a)[N_SEG] = (float(*)[N_SEG])SMEM;   // [4][256]
        const int m0 = bid * 4;
        for (int l = tid; l < 4 * N_SEG; l += 512) {
            int mm = l >> 8, s = l & 255;
            int m = m0 + mm;
            float inv = 1.f / fmaxf(g_cnt[s], 1.f);
            a[mm][s] = (m < N_CLASS) ? g_att[m * N_SEG + s] * inv : 0.f;
        }
        __syncthreads();
        int d = tid;
        float a0 = 0.f, a1 = 0.f, a2 = 0.f, a3 = 0.f;
        #pragma unroll 8
        for (int s = 0; s < N_SEG; s++) {
            float xv = g_segsum[s * D_LEN + d];
            a0 += xv * a[0][s];
            a1 += xv * a[1][s];
            a2 += xv * a[2][s];
            a3 += xv * a[3][s];
        }
        if (m0 + 0 < N_CLASS) g_fk[(m0 + 0) * D_LEN + d] = a0;
        if (m0 + 1 < N_CLASS) g_fk[(m0 + 1) * D_LEN + d] = a1;
        if (m0 + 2 < N_CLASS) g_fk[(m0 + 2) * D_LEN + d] = a2;
        if (m0 + 3 < N_CLASS) g_fk[(m0 + 3) * D_LEN + d] = a3;
    }
    grid_barrier(2);

    // ===================== phase 4: keystep attention + categories (block 0) =====================
    if (bid == 0) {
        float* s2    = SMEM;          // 128
        float* alpha = SMEM + 128;    // 128
        float* fv    = SMEM + 256;    // 512

        for (int m = warp; m < N_CLASS; m += 16) {
            float acc = 0.f;
            const float* fm = g_fk + m * D_LEN;
            #pragma unroll 4
            for (int d = lane; d < D_LEN; d += 32) acc += fm[d] * att2_w[d];
            #pragma unroll
            for (int o = 16; o; o >>= 1) acc += __shfl_xor_sync(0xffffffffu, acc, o);
            if (!lane) s2[m] = acc + att2_b[0];
        }
        __syncthreads();

        if (warp == 0) {
            float v[4], mx = -1e30f;
            #pragma unroll
            for (int q = 0; q < 4; q++) {
                int m = lane + 32 * q;
                v[q] = (m < N_CLASS) ? s2[m] : -1e30f;
                mx = fmaxf(mx, v[q]);
            }
            #pragma unroll
            for (int o = 16; o; o >>= 1) mx = fmaxf(mx, __shfl_xor_sync(0xffffffffu, mx, o));
            float e[4], sum = 0.f;
            #pragma unroll
            for (int q = 0; q < 4; q++) {
                int m = lane + 32 * q;
                e[q] = (m < N_CLASS) ? __expf(v[q] - mx) : 0.f;
                sum += e[q];
            }
            #pragma unroll
            for (int o = 16; o; o >>= 1) sum += __shfl_xor_sync(0xffffffffu, sum, o);
            float inv = 1.f / sum;
            #pragma unroll
            for (int q = 0; q < 4; q++) {
                int m = lane + 32 * q;
                if (m < N_CLASS) {
                    float a = e[q] * inv;
                    alpha[m] = a;
                    out_aks[m] = a;
                }
            }
        }
        __syncthreads();

        {
            int d = tid;
            float acc = 0.f;
            #pragma unroll 8
            for (int m = 0; m < N_CLASS; m++) acc += g_fk[m * D_LEN + d] * alpha[m];
            fv[d] = acc;
        }
        __syncthreads();

        for (int c = warp; c < N_CAT; c += 16) {
            float acc = 0.f;
            #pragma unroll 4
            for (int d = lane; d < D_LEN; d += 32) acc += fv[d] * cls_w[d * N_CAT + c];
            #pragma unroll
            for (int o = 16; o; o >>= 1) acc += __shfl_xor_sync(0xffffffffu, acc, o);
            if (!lane) out_cats[c] = acc + cls_b[c];
        }
    }
}

// ---------------- launch ----------------
extern "C" void kernel_launch(void* const* d_in, const int* in_sizes, int n_in,
                              void* d_out, int out_size) {
    const float* feature = (const float*)d_in[0];
    const int*   seg_ids = (const int*)d_in[1];
    const float* att_w   = (const float*)d_in[2];
    const float* att_b   = (const float*)d_in[3];
    const float* att2_w  = (const float*)d_in[4];
    const float* att2_b  = (const float*)d_in[5];
    const float* fcsn_w1 = (const float*)d_in[6];
    const float* fcsn_b1 = (const float*)d_in[7];
    const float* fcsn_w2 = (const float*)d_in[8];
    const float* fcsn_b2 = (const float*)d_in[9];
    const float* cls_w   = (const float*)d_in[10];
    const float* cls_b   = (const float*)d_in[11];

    float* out = (float*)d_out;
    float* out_ks   = out + OUT_KS;
    float* out_cats = out + OUT_CATS;
    float* out_asp  = out + OUT_ASP;
    float* out_aks  = out + OUT_AKS;

    {
        dim3 g(16, 16, 4), b(32, 8);
        k_prep<<<g, b>>>(fcsn_w1);
    }
    k_spatial<<<T_LEN, 256>>>(feature, seg_ids, att_w, att_b, out_asp);
    k_tail<<<NB, 512>>>(fcsn_b1, fcsn_w2, fcsn_b2,
                        att2_w, att2_b, cls_w, cls_b,
                        out_ks, out_aks, out_cats);
}

// round 17
// speedup vs baseline: 1.1089x; 1.1089x over previous
#include <cuda_runtime.h>
#include <cuda_bf16.h>
#include <cstdint>
#include <math.h>

// ---------------- problem constants ----------------
#define T_LEN   4096
#define R_LEN   49
#define D_LEN   512
#define N_SEG   256
#define N_CLASS 106
#define N_CAT   18

#define FEAT_FLOATS (R_LEN * D_LEN)       // 25088

// output layout: keysteps[106*256], cats[18], alphas_sp[4096*49], alphas_ks[106]
#define OUT_KS   0
#define OUT_CATS (N_CLASS * N_SEG)
#define OUT_ASP  (OUT_CATS + N_CAT)
#define OUT_AKS  (OUT_ASP + T_LEN * R_LEN)

#define NB 128     // tail grid size (co-resident: 128 <= 148 SMs at 1 block/SM)

// ---------------- scratch ----------------
__device__ float g_segsum[N_SEG * D_LEN];     // [s][d]
__device__ float g_cnt[N_SEG];
__device__ float g_w1t[3 * D_LEN * D_LEN];    // w1 transposed: [k][i][o]
__device__ float g_hacc[D_LEN * N_SEG];       // conv1 pre-activation accumulator: [o][s]
__device__ float g_att[N_CLASS * N_SEG];      // softmax over classes: [m][s]
__device__ float g_y[N_SEG];                  // y[s]   = (1/cnt_s) <segsum[s,:], att2_w>
__device__ float g_z[N_SEG * N_CAT];          // z[s][c]= (1/cnt_s) <segsum[s,:], cls_w[:,c]>
__device__ unsigned g_bar[4];                 // grid barrier counters

// ---------------- K_prep: zero accumulators + transpose w1 + reset barriers ----------------
__global__ void k_prep(const float* __restrict__ w1) {
    __shared__ float tl[32][33];
    const int z = blockIdx.z;
    const int tx = threadIdx.x, ty = threadIdx.y;
    if (z < 3) {
        const int o0 = blockIdx.x * 32, i0 = blockIdx.y * 32, k = z;
        #pragma unroll
        for (int j = ty; j < 32; j += 8)
            tl[j][tx] = w1[(size_t)(o0 + j) * (D_LEN * 3) + (i0 + tx) * 3 + k];
        __syncthreads();
        #pragma unroll
        for (int j = ty; j < 32; j += 8)
            g_w1t[((size_t)k * D_LEN + i0 + j) * D_LEN + o0 + tx] = tl[tx][j];
    } else {
        const int bid = blockIdx.y * 16 + blockIdx.x;   // 0..255
        const int i = bid * 256 + ty * 32 + tx;         // 0..65535
        g_segsum[i] = 0.f;           g_hacc[i] = 0.f;
        g_segsum[i + 65536] = 0.f;   g_hacc[i + 65536] = 0.f;
        if (i < N_SEG) g_cnt[i] = 0.f;
        if (i < 4) g_bar[i] = 0u;
    }
}

// ---------------- K1: spatial attention + segment accumulation (champion; unchanged) ----------------
__global__ void __launch_bounds__(256)
k_spatial(const float* __restrict__ feature,
          const int* __restrict__ seg_ids,
          const float* __restrict__ att_w,
          const float* __restrict__ att_b,
          float* __restrict__ alphas_out) {
    __shared__ float sv[64];

    const int t = blockIdx.x;
    const int tid = threadIdx.x;
    const int warp = tid >> 5, lane = tid & 31;
    const float* fbase = feature + (size_t)t * FEAT_FLOATS;
    const float4* f4 = (const float4*)fbase;

    float4 w4[4];
    {
        const float4* wv = (const float4*)att_w;
        #pragma unroll
        for (int j = 0; j < 4; j++) w4[j] = wv[lane + 32 * j];
    }
    const float ab = att_b[0];

    for (int r = warp; r < R_LEN; r += 8) {
        const float4* fr = f4 + r * 128;
        float acc = 0.f;
        #pragma unroll
        for (int j = 0; j < 4; j++) {
            float4 v = fr[lane + 32 * j];
            acc += v.x * w4[j].x + v.y * w4[j].y + v.z * w4[j].z + v.w * w4[j].w;
        }
        #pragma unroll
        for (int o = 16; o; o >>= 1) acc += __shfl_xor_sync(0xffffffffu, acc, o);
        if (!lane) sv[r] = acc + ab;
    }
    __syncthreads();

    if (warp == 0) {
        float v0 = sv[lane];
        float v1 = (lane + 32 < R_LEN) ? sv[lane + 32] : -1e30f;
        float mx = fmaxf(v0, v1);
        #pragma unroll
        for (int o = 16; o; o >>= 1) mx = fmaxf(mx, __shfl_xor_sync(0xffffffffu, mx, o));
        float e0 = __expf(v0 - mx);
        float e1 = (lane + 32 < R_LEN) ? __expf(v1 - mx) : 0.f;
        float sum = e0 + e1;
        #pragma unroll
        for (int o = 16; o; o >>= 1) sum += __shfl_xor_sync(0xffffffffu, sum, o);
        float inv = 1.f / sum;
        {
            float a = e0 * inv;
            sv[lane] = a;
            alphas_out[t * R_LEN + lane] = a;
        }
        if (lane + 32 < R_LEN) {
            float a = e1 * inv;
            sv[lane + 32] = a;
            alphas_out[t * R_LEN + lane + 32] = a;
        }
    }
    __syncthreads();

    {
        const float2* f2 = (const float2*)fbase;
        float ax = 0.f, ay = 0.f;
        #pragma unroll 7
        for (int r = 0; r < R_LEN; r++) {
            float a = sv[r];
            float2 v = f2[r * 256 + tid];
            ax += v.x * a;
            ay += v.y * a;
        }
        const int seg = __ldg(&seg_ids[t]);
        float* dst = &g_segsum[seg * D_LEN + tid * 2];
        atomicAdd(dst + 0, ax);
        atomicAdd(dst + 1, ay);
        if (tid == 0) atomicAdd(&g_cnt[seg], 1.f);
    }
}

// ---------------- grid barrier (all NB blocks co-resident) ----------------
__device__ __forceinline__ void grid_barrier(int idx) {
    __syncthreads();
    if (threadIdx.x == 0) {
        __threadfence();
        atomicAdd(&g_bar[idx], 1u);
        while (*(volatile unsigned*)&g_bar[idx] < (unsigned)NB) { __nanosleep(32); }
        __threadfence();
    }
    __syncthreads();
}

// ---------------- K_tail: conv1 -> {conv2+softmax | y,z} -> finale, one kernel ----------------
// 128 blocks x 512 threads; 2 grid barriers (phase 3 eliminated algebraically).
#define CWW 68    // Wt row stride (32x64 tile)
#define CWX 132   // Xt row stride (32x128 tile)
#define P2J 4     // conv2 columns per block
#define P2S 5     // conv2 smem pad stride
__global__ void __launch_bounds__(512, 1)
k_tail(const float* __restrict__ b1,
       const float* __restrict__ w2,
       const float* __restrict__ b2,
       const float* __restrict__ att2_w,
       const float* __restrict__ att2_b,
       const float* __restrict__ cls_w,
       const float* __restrict__ cls_b,
       float* __restrict__ out_ks,
       float* __restrict__ out_aks,
       float* __restrict__ out_cats) {
    __shared__ float SMEM[6600];   // 26.4KB, aliased per phase

    const int bid = blockIdx.x;
    const int tid = threadIdx.x;
    const int warp = tid >> 5, lane = tid & 31;

    // ===================== phase 1: conv1 (split-K GEMM, 128 jobs) =====================
    // job = (8 o-tiles of 64) x (2 s-tiles of 128) x (8 splits of 6 k-chunks)
    {
        float* Wt   = SMEM;                  // 32 x 64 (stride 68)
        float* Xt   = SMEM + 32 * CWW;       // 32 x 128 (stride 132)
        float* icnt = Xt + 32 * CWX;         // 130 entries

        const int ot = bid & 7;
        const int st = (bid >> 3) & 1;
        const int sp = bid >> 4;             // 0..7
        const int o0 = ot * 64, s0 = st * 128;
        const int tx = tid & 31, ty = tid >> 5;

        float acc[4][4];
        #pragma unroll
        for (int a = 0; a < 4; a++)
            #pragma unroll
            for (int b = 0; b < 4; b++) acc[a][b] = 0.f;

        if (tid < 130) {
            int sc = s0 + tid - 1;
            float c = (sc >= 0 && sc < N_SEG) ? fmaxf(g_cnt[sc], 1.f) : 1.f;
            icnt[tid] = 1.f / c;
        }
        __syncthreads();

        #pragma unroll 1
        for (int c = sp * 6; c < sp * 6 + 6; c++) {
            const int k = c >> 4;
            const int ic = (c & 15) * 32;
            #pragma unroll
            for (int l = tid; l < 2048; l += 512) {          // Wt: 32x64
                int ii = l >> 6, oo = l & 63;
                Wt[ii * CWW + oo] = g_w1t[((size_t)k * D_LEN + ic + ii) * D_LEN + o0 + oo];
            }
            #pragma unroll
            for (int l = tid; l < 4096; l += 512) {          // Xt: 32x128
                int ii = l & 31, ss = l >> 5;
                int sc = s0 + ss + k - 1;
                float v = (sc >= 0 && sc < N_SEG) ? g_segsum[sc * D_LEN + ic + ii] : 0.f;
                Xt[ii * CWX + ss] = v * icnt[ss + k];
            }
            __syncthreads();
            #pragma unroll
            for (int ii = 0; ii < 32; ii++) {
                float4 wv = *(const float4*)&Wt[ii * CWW + ty * 4];
                float4 xv = *(const float4*)&Xt[ii * CWX + tx * 4];
                acc[0][0] += wv.x * xv.x; acc[0][1] += wv.x * xv.y;
                acc[0][2] += wv.x * xv.z; acc[0][3] += wv.x * xv.w;
                acc[1][0] += wv.y * xv.x; acc[1][1] += wv.y * xv.y;
                acc[1][2] += wv.y * xv.z; acc[1][3] += wv.y * xv.w;
                acc[2][0] += wv.z * xv.x; acc[2][1] += wv.z * xv.y;
                acc[2][2] += wv.z * xv.z; acc[2][3] += wv.z * xv.w;
                acc[3][0] += wv.w * xv.x; acc[3][1] += wv.w * xv.y;
                acc[3][2] += wv.w * xv.z; acc[3][3] += wv.w * xv.w;
            }
            __syncthreads();
        }
        #pragma unroll
        for (int a = 0; a < 4; a++) {
            float* dst = &g_hacc[(o0 + ty * 4 + a) * N_SEG + s0 + tx * 4];
            #pragma unroll
            for (int b = 0; b < 4; b++) atomicAdd(dst + b, acc[a][b]);
        }
    }
    grid_barrier(0);

    // ===================== phase 2: blocks 0-63: conv2+softmax; blocks 64-127: y,z =====================
    if (bid < 64) {
        float* hc = SMEM;                     // [512][P2S]
        float* lg = SMEM + D_LEN * P2S;       // [112][P2S]
        const int s0 = bid * P2J;

        for (int l = tid; l < D_LEN * P2J; l += 512) {
            int i = l >> 2, j = l & 3;
            hc[i * P2S + j] = fmaxf(g_hacc[i * N_SEG + s0 + j] + b1[i], 0.f);
        }
        __syncthreads();

        for (int m = warp; m < N_CLASS; m += 16) {
            float acc[P2J] = {0.f, 0.f, 0.f, 0.f};
            const float* wm = w2 + m * D_LEN;
            #pragma unroll 4
            for (int i = lane; i < D_LEN; i += 32) {
                float wv = wm[i];
                const float* hp = &hc[i * P2S];
                #pragma unroll
                for (int j = 0; j < P2J; j++) acc[j] += wv * hp[j];
            }
            #pragma unroll
            for (int j = 0; j < P2J; j++) {
                float a = acc[j];
                #pragma unroll
                for (int o = 16; o; o >>= 1) a += __shfl_xor_sync(0xffffffffu, a, o);
                acc[j] = a;
            }
            if (!lane) {
                float bb = b2[m];
                #pragma unroll
                for (int j = 0; j < P2J; j++) lg[m * P2S + j] = acc[j] + bb;
            }
        }
        __syncthreads();

        if (warp < P2J) {
            int j = warp;
            int s = s0 + j;
            float v[4], mx = -1e30f;
            #pragma unroll
            for (int q = 0; q < 4; q++) {
                int m = lane + 32 * q;
                v[q] = (m < N_CLASS) ? lg[m * P2S + j] : -1e30f;
                mx = fmaxf(mx, v[q]);
            }
            #pragma unroll
            for (int o = 16; o; o >>= 1) mx = fmaxf(mx, __shfl_xor_sync(0xffffffffu, mx, o));
            float e[4], sum = 0.f;
            #pragma unroll
            for (int q = 0; q < 4; q++) {
                int m = lane + 32 * q;
                e[q] = (m < N_CLASS) ? __expf(v[q] - mx) : 0.f;
                sum += e[q];
            }
            #pragma unroll
            for (int o = 16; o; o >>= 1) sum += __shfl_xor_sync(0xffffffffu, sum, o);
            float inv = 1.f / sum;
            #pragma unroll
            for (int q = 0; q < 4; q++) {
                int m = lane + 32 * q;
                if (m < N_CLASS) {
                    out_ks[m * N_SEG + s] = v[q];
                    g_att[m * N_SEG + s] = e[q] * inv;
                }
            }
        }
    } else {
        // blocks 64..127: compute y[s] and z[s][c] for 4 s-values each.
        // task layout: 4 s x 19 dots (c=0..17 -> z, c==18 -> y), 16 warps strided.
        const int sb = (bid - 64) * 4;
        for (int task = warp; task < 4 * 19; task += 16) {
            const int si = task / 19;
            const int c = task - si * 19;
            const int s = sb + si;
            const float invc = 1.f / fmaxf(g_cnt[s], 1.f);
            const float* xr = &g_segsum[s * D_LEN];
            float acc = 0.f;
            if (c == 18) {
                #pragma unroll 4
                for (int d = lane; d < D_LEN; d += 32) acc += xr[d] * att2_w[d];
            } else {
                #pragma unroll 4
                for (int d = lane; d < D_LEN; d += 32) acc += xr[d] * cls_w[d * N_CAT + c];
            }
            #pragma unroll
            for (int o = 16; o; o >>= 1) acc += __shfl_xor_sync(0xffffffffu, acc, o);
            if (!lane) {
                if (c == 18) g_y[s] = acc * invc;
                else         g_z[s * N_CAT + c] = acc * invc;
            }
        }
    }
    grid_barrier(1);

    // ===================== phase 3 (finale, block 0): s2 -> softmax -> beta -> cats =====================
    if (bid == 0) {
        float* ys    = SMEM;          // 256: y
        float* s2    = SMEM + 256;    // 128
        float* alpha = SMEM + 384;    // 128
        float* beta  = SMEM + 512;    // 256

        for (int s = tid; s < N_SEG; s += 512) ys[s] = g_y[s];
        __syncthreads();

        // s2[m] = sum_s att[m][s] * y[s] + att2_b
        for (int m = warp; m < N_CLASS; m += 16) {
            const float* am = &g_att[m * N_SEG];
            float acc = 0.f;
            #pragma unroll
            for (int s = lane; s < N_SEG; s += 32) acc += am[s] * ys[s];
            #pragma unroll
            for (int o = 16; o; o >>= 1) acc += __shfl_xor_sync(0xffffffffu, acc, o);
            if (!lane) s2[m] = acc + att2_b[0];
        }
        __syncthreads();

        // softmax over 106 classes (warp 0) -> alpha, out_aks
        if (warp == 0) {
            float v[4], mx = -1e30f;
            #pragma unroll
            for (int q = 0; q < 4; q++) {
                int m = lane + 32 * q;
                v[q] = (m < N_CLASS) ? s2[m] : -1e30f;
                mx = fmaxf(mx, v[q]);
            }
            #pragma unroll
            for (int o = 16; o; o >>= 1) mx = fmaxf(mx, __shfl_xor_sync(0xffffffffu, mx, o));
            float e[4], sum = 0.f;
            #pragma unroll
            for (int q = 0; q < 4; q++) {
                int m = lane + 32 * q;
                e[q] = (m < N_CLASS) ? __expf(v[q] - mx) : 0.f;
                sum += e[q];
            }
            #pragma unroll
            for (int o = 16; o; o >>= 1) sum += __shfl_xor_sync(0xffffffffu, sum, o);
            float inv = 1.f / sum;
            #pragma unroll
            for (int q = 0; q < 4; q++) {
                int m = lane + 32 * q;
                if (m < N_CLASS) {
                    float a = e[q] * inv;
                    alpha[m] = a;
                    out_aks[m] = a;
                }
            }
        }
        __syncthreads();

        // beta[s] = sum_m alpha[m] * att[m][s]  (coalesced over s)
        if (tid < N_SEG) {
            float acc = 0.f;
            #pragma unroll 2
            for (int m = 0; m < N_CLASS; m++) acc += alpha[m] * g_att[m * N_SEG + tid];
            beta[tid] = acc;
        }
        __syncthreads();

        // cats[c] = sum_s beta[s] * z[s][c] + cls_b[c]
        for (int c = warp; c < N_CAT; c += 16) {
            float acc = 0.f;
            #pragma unroll
            for (int s = lane; s < N_SEG; s += 32) acc += beta[s] * g_z[s * N_CAT + c];
            #pragma unroll
            for (int o = 16; o; o >>= 1) acc += __shfl_xor_sync(0xffffffffu, acc, o);
            if (!lane) out_cats[c] = acc + cls_b[c];
        }
    }
}

// ---------------- launch ----------------
extern "C" void kernel_launch(void* const* d_in, const int* in_sizes, int n_in,
                              void* d_out, int out_size) {
    const float* feature = (const float*)d_in[0];
    const int*   seg_ids = (const int*)d_in[1];
    const float* att_w   = (const float*)d_in[2];
    const float* att_b   = (const float*)d_in[3];
    const float* att2_w  = (const float*)d_in[4];
    const float* att2_b  = (const float*)d_in[5];
    const float* fcsn_w1 = (const float*)d_in[6];
    const float* fcsn_b1 = (const float*)d_in[7];
    const float* fcsn_w2 = (const float*)d_in[8];
    const float* fcsn_b2 = (const float*)d_in[9];
    const float* cls_w   = (const float*)d_in[10];
    const float* cls_b   = (const float*)d_in[11];

    float* out = (float*)d_out;
    float* out_ks   = out + OUT_KS;
    float* out_cats = out + OUT_CATS;
    float* out_asp  = out + OUT_ASP;
    float* out_aks  = out + OUT_AKS;

    {
        dim3 g(16, 16, 4), b(32, 8);
        k_prep<<<g, b>>>(fcsn_w1);
    }
    k_spatial<<<T_LEN, 256>>>(feature, seg_ids, att_w, att_b, out_asp);
    k_tail<<<NB, 512>>>(fcsn_b1, fcsn_w2, fcsn_b2,
                        att2_w, att2_b, cls_w, cls_b,
                        out_ks, out_aks, out_cats);
}